// round 3
// baseline (speedup 1.0000x reference)
#include <cuda_runtime.h>
#include <math.h>

#define NN 50000
#define NE 800000
#define FULLM 0xffffffffu

// ---------------- device scratch ----------------
__device__ float d_Q[NN * 64];
__device__ float d_K[NN * 64];
__device__ float d_V[NN * 64];
__device__ float d_sbuf[NE * 64];
__device__ float d_scoreb[NE * 8];
__device__ float d_epre[NE * 64];
__device__ float d_t1[NN * 64];
__device__ float d_t2[NN * 64];
__device__ int   d_rowoff[NN + 1];
__device__ int   d_counts[NN];
__device__ int   d_cursor[NN];
__device__ int   d_col[NE];
// [0:64) e-sum [64:128) e-sumsq [128:192) t1-sum [192:256) t1-sumsq
// [256:320) t2-sum [320:384) t2-sumsq
__device__ float d_stats[384];

__device__ __forceinline__ unsigned cvt_tf32(float x) {
    unsigned r;
    asm("cvt.rna.tf32.f32 %0, %1;" : "=r"(r) : "f"(x));
    return r;
}

#define MMA_TF32(C, A0, A1, A2, A3, B0, B1)                                   \
    asm volatile(                                                             \
        "mma.sync.aligned.m16n8k8.row.col.f32.tf32.tf32.f32 "                 \
        "{%0,%1,%2,%3}, {%4,%5,%6,%7}, {%8,%9}, {%0,%1,%2,%3};"               \
        : "+f"(C[0]), "+f"(C[1]), "+f"(C[2]), "+f"(C[3])                      \
        : "r"(A0), "r"(A1), "r"(A2), "r"(A3), "r"(B0), "r"(B1))

// ---------------- zero ----------------
__global__ void k_zero() {
    int i = blockIdx.x * blockDim.x + threadIdx.x;
    if (i < NN) d_counts[i] = 0;
    if (i < 384) d_stats[i] = 0.f;
}

// ---------------- CSR build ----------------
__global__ void k_count(const int* __restrict__ eidx) {
    int e = blockIdx.x * blockDim.x + threadIdx.x;
    if (e < NE) atomicAdd(&d_counts[eidx[NE + e]], 1);
}

__global__ void k_scan() {
    __shared__ int sh[1024];
    int tid = threadIdx.x;
    const int per = (NN + 1023) / 1024;
    int s = tid * per;
    int e = s + per; if (e > NN) e = NN;
    int sum = 0;
    for (int i = s; i < e && i < NN; i++) sum += d_counts[i];
    sh[tid] = sum;
    __syncthreads();
    for (int off = 1; off < 1024; off <<= 1) {
        int t = (tid >= off) ? sh[tid - off] : 0;
        __syncthreads();
        sh[tid] += t;
        __syncthreads();
    }
    int run = sh[tid] - sum;
    for (int i = s; i < e && i < NN; i++) {
        d_rowoff[i] = run;
        d_cursor[i] = run;
        run += d_counts[i];
    }
    if (tid == 1023) d_rowoff[NN] = sh[1023];
}

__global__ void k_fill(const int* __restrict__ eidx) {
    int e = blockIdx.x * blockDim.x + threadIdx.x;
    if (e < NE) {
        int dst = eidx[NE + e];
        int p = atomicAdd(&d_cursor[dst], 1);
        d_col[p] = e;
    }
}

// ---------------- Q,K,V node GEMM ----------------
__global__ void __launch_bounds__(256) k_qkv(const float* __restrict__ x,
                                             const float* __restrict__ Wq,
                                             const float* __restrict__ bq,
                                             const float* __restrict__ Wk,
                                             const float* __restrict__ Wv) {
    __shared__ float sWq[4096], sWk[4096], sWv[4096];
    int tid = threadIdx.x;
    for (int i = tid; i < 4096; i += 256) { sWq[i] = Wq[i]; sWk[i] = Wk[i]; sWv[i] = Wv[i]; }
    __syncthreads();
    int l = tid & 31, w = tid >> 5;
    float bq0 = bq[l], bq1 = bq[l + 32];
    int nbase = (blockIdx.x * 8 + w) * 4;
    for (int r = 0; r < 4; r++) {
        int n = nbase + r;
        if (n >= NN) break;
        float x0 = x[n * 64 + l], x1 = x[n * 64 + 32 + l];
        float q0 = bq0, q1 = bq1, k0 = 0.f, k1 = 0.f, v0 = 0.f, v1 = 0.f;
#pragma unroll
        for (int d = 0; d < 32; d++) {
            float xv = __shfl_sync(FULLM, x0, d);
            q0 += xv * sWq[d * 64 + l]; q1 += xv * sWq[d * 64 + 32 + l];
            k0 += xv * sWk[d * 64 + l]; k1 += xv * sWk[d * 64 + 32 + l];
            v0 += xv * sWv[d * 64 + l]; v1 += xv * sWv[d * 64 + 32 + l];
        }
#pragma unroll
        for (int d = 0; d < 32; d++) {
            float xv = __shfl_sync(FULLM, x1, d);
            q0 += xv * sWq[(d + 32) * 64 + l]; q1 += xv * sWq[(d + 32) * 64 + 32 + l];
            k0 += xv * sWk[(d + 32) * 64 + l]; k1 += xv * sWk[(d + 32) * 64 + 32 + l];
            v0 += xv * sWv[(d + 32) * 64 + l]; v1 += xv * sWv[(d + 32) * 64 + 32 + l];
        }
        d_Q[n * 64 + l] = q0; d_Q[n * 64 + 32 + l] = q1;
        d_K[n * 64 + l] = k0; d_K[n * 64 + 32 + l] = k1;
        d_V[n * 64 + l] = v0; d_V[n * 64 + 32 + l] = v1;
    }
}

// ---------------- edge kernel: tf32 mma ----------------
__global__ void __launch_bounds__(256) k_edge_mma(const float* __restrict__ ea,
                                                  const int* __restrict__ eidx,
                                                  const float* __restrict__ We,
                                                  const float* __restrict__ be,
                                                  const float* __restrict__ Aw,
                                                  const float* __restrict__ WOe,
                                                  const float* __restrict__ bOe) {
    extern __shared__ float smem[];
    float* sA     = smem;              // 128 x 68
    float* sWeT   = smem + 8704;       // 128 x 68
    float* sWOeT  = smem + 17408;      // 64 x 68
    float* sStats = smem + 21760;      // 128

    const int tid = threadIdx.x;
    const int tileBase = blockIdx.x * 128;

    if (tid < 128) sStats[tid] = 0.f;
    for (int i = tid; i < 8192; i += 256) {
        int r = i >> 6, c = i & 63;
        sA[r * 68 + c] = ea[(size_t)tileBase * 64 + i];
    }
    for (int i = tid; i < 8192; i += 256) {
        int k = i >> 7, n = i & 127;
        int t7 = k & 7;
        int kd = (k & ~7) + ((t7 & 3) << 1) + (t7 >> 2);
        sWeT[n * 68 + kd] = __uint_as_float(cvt_tf32(We[i]));
    }
    for (int i = tid; i < 4096; i += 256) {
        int k = i >> 6, n = i & 63;
        int t7 = k & 7;
        int kd = (k & ~7) + ((t7 & 3) << 1) + (t7 >> 2);
        sWOeT[n * 68 + kd] = __uint_as_float(cvt_tf32(WOe[i]));
    }
    __syncthreads();

    const int l = tid & 31;
    const int w16 = (tid >> 5) * 16;
    const int g = l >> 2, tig = l & 3;
    const int rowA0 = (w16 + g) * 68;
    const int rowA1 = rowA0 + 8 * 68;

    // ---- GEMM1 ----
    float c1[16][4];
#pragma unroll
    for (int nt = 0; nt < 16; nt++)
#pragma unroll
        for (int s = 0; s < 4; s++) c1[nt][s] = 0.f;

#pragma unroll
    for (int ks = 0; ks < 8; ks++) {
        unsigned a0 = cvt_tf32(sA[rowA0 + ks * 8 + tig]);
        unsigned a1 = cvt_tf32(sA[rowA1 + ks * 8 + tig]);
        unsigned a2 = cvt_tf32(sA[rowA0 + ks * 8 + tig + 4]);
        unsigned a3 = cvt_tf32(sA[rowA1 + ks * 8 + tig + 4]);
#pragma unroll
        for (int nt = 0; nt < 16; nt++) {
            float2 bb = *(const float2*)&sWeT[(nt * 8 + g) * 68 + ks * 8 + 2 * tig];
            MMA_TF32(c1[nt], a0, a1, a2, a3, __float_as_uint(bb.x), __float_as_uint(bb.y));
        }
    }

    // ---- init C2 with ea + bOe ----
    float c2[8][4];
#pragma unroll
    for (int nt = 0; nt < 8; nt++) {
        int col = nt * 8 + 2 * tig;
        float2 e0v = *(const float2*)&sA[rowA0 + col];
        float2 e1v = *(const float2*)&sA[rowA1 + col];
        float bo0 = __ldg(&bOe[col]), bo1 = __ldg(&bOe[col + 1]);
        c2[nt][0] = e0v.x + bo0; c2[nt][1] = e0v.y + bo1;
        c2[nt][2] = e1v.x + bo0; c2[nt][3] = e1v.y + bo1;
    }
    __syncwarp();

    // ---- epilogue 1 ----
    const int e0 = tileBase + w16 + g;
    const int e1 = e0 + 8;
    int src0 = eidx[e0], dst0 = eidx[NE + e0];
    int src1 = eidx[e1], dst1 = eidx[NE + e1];
    const float* K0 = d_K + (size_t)src0 * 64;
    const float* Q0 = d_Q + (size_t)dst0 * 64;
    const float* K1 = d_K + (size_t)src1 * 64;
    const float* Q1 = d_Q + (size_t)dst1 * 64;

#pragma unroll
    for (int h = 0; h < 8; h++) {
        const int nt = 2 * h;
        const int dc = h * 8 + 2 * tig;
        float2 ka = *(const float2*)(K0 + dc);
        float2 qa = *(const float2*)(Q0 + dc);
        float2 kb = *(const float2*)(K1 + dc);
        float2 qb = *(const float2*)(Q1 + dc);
        float kq00 = ka.x + qa.x, kq01 = ka.y + qa.y;
        float kq10 = kb.x + qb.x, kq11 = kb.y + qb.y;
        float bw0 = __ldg(&be[h * 16 + 2 * tig]);
        float bw1 = __ldg(&be[h * 16 + 2 * tig + 1]);
        float bb0 = __ldg(&be[h * 16 + 8 + 2 * tig]);
        float bb1 = __ldg(&be[h * 16 + 9 + 2 * tig]);
        float aw0 = __ldg(&Aw[(2 * tig) * 8 + h]);
        float aw1 = __ldg(&Aw[(2 * tig + 1) * 8 + h]);

        float t00 = kq00 * (c1[nt][0] + bw0);
        float t01 = kq01 * (c1[nt][1] + bw1);
        float t10 = kq10 * (c1[nt][2] + bw0);
        float t11 = kq11 * (c1[nt][3] + bw1);
        float s00 = fmaxf(copysignf(sqrtf(fabsf(t00)), t00) + (c1[nt + 1][0] + bb0), 0.f);
        float s01 = fmaxf(copysignf(sqrtf(fabsf(t01)), t01) + (c1[nt + 1][1] + bb1), 0.f);
        float s10 = fmaxf(copysignf(sqrtf(fabsf(t10)), t10) + (c1[nt + 1][2] + bb0), 0.f);
        float s11 = fmaxf(copysignf(sqrtf(fabsf(t11)), t11) + (c1[nt + 1][3] + bb1), 0.f);

        *(float2*)&d_sbuf[(size_t)e0 * 64 + dc] = make_float2(s00, s01);
        *(float2*)&d_sbuf[(size_t)e1 * 64 + dc] = make_float2(s10, s11);
        *(float2*)&sA[rowA0 + dc] = make_float2(s00, s01);
        *(float2*)&sA[rowA1 + dc] = make_float2(s10, s11);

        float p0 = s00 * aw0 + s01 * aw1;
        float p1 = s10 * aw0 + s11 * aw1;
        p0 += __shfl_xor_sync(FULLM, p0, 1);
        p0 += __shfl_xor_sync(FULLM, p0, 2);
        p1 += __shfl_xor_sync(FULLM, p1, 1);
        p1 += __shfl_xor_sync(FULLM, p1, 2);
        if (tig == 0) {
            d_scoreb[(size_t)e0 * 8 + h] = fminf(fmaxf(p0, -5.f), 5.f);
            d_scoreb[(size_t)e1 * 8 + h] = fminf(fmaxf(p1, -5.f), 5.f);
        }
    }
    __syncwarp();

    // ---- GEMM2 ----
#pragma unroll
    for (int ks = 0; ks < 8; ks++) {
        unsigned a0 = cvt_tf32(sA[rowA0 + ks * 8 + tig]);
        unsigned a1 = cvt_tf32(sA[rowA1 + ks * 8 + tig]);
        unsigned a2 = cvt_tf32(sA[rowA0 + ks * 8 + tig + 4]);
        unsigned a3 = cvt_tf32(sA[rowA1 + ks * 8 + tig + 4]);
#pragma unroll
        for (int nt = 0; nt < 8; nt++) {
            float2 bb = *(const float2*)&sWOeT[(nt * 8 + g) * 68 + ks * 8 + 2 * tig];
            MMA_TF32(c2[nt], a0, a1, a2, a3, __float_as_uint(bb.x), __float_as_uint(bb.y));
        }
    }

    // ---- epilogue 2: store epre + BN stats (smem staged) ----
#pragma unroll
    for (int nt = 0; nt < 8; nt++) {
        int col = nt * 8 + 2 * tig;
        *(float2*)&d_epre[(size_t)e0 * 64 + col] = make_float2(c2[nt][0], c2[nt][1]);
        *(float2*)&d_epre[(size_t)e1 * 64 + col] = make_float2(c2[nt][2], c2[nt][3]);
        float s0 = c2[nt][0] + c2[nt][2];
        float s1 = c2[nt][1] + c2[nt][3];
        float q0 = c2[nt][0] * c2[nt][0] + c2[nt][2] * c2[nt][2];
        float q1 = c2[nt][1] * c2[nt][1] + c2[nt][3] * c2[nt][3];
#pragma unroll
        for (int off = 4; off < 32; off <<= 1) {
            s0 += __shfl_xor_sync(FULLM, s0, off);
            s1 += __shfl_xor_sync(FULLM, s1, off);
            q0 += __shfl_xor_sync(FULLM, q0, off);
            q1 += __shfl_xor_sync(FULLM, q1, off);
        }
        if (l < 4) {
            atomicAdd(&sStats[col], s0);
            atomicAdd(&sStats[col + 1], s1);
            atomicAdd(&sStats[64 + col], q0);
            atomicAdd(&sStats[64 + col + 1], q1);
        }
    }
    __syncthreads();
    if (tid < 64) {
        atomicAdd(&d_stats[tid], sStats[tid]);
        atomicAdd(&d_stats[64 + tid], sStats[64 + tid]);
    }
}

// ---------------- fused node kernel: attention gather + WOh GEMM + BN1h stats
__global__ void __launch_bounds__(256) k_node_h1(const int* __restrict__ eidx,
                                                 const float* __restrict__ VeRow,
                                                 const float* __restrict__ dcoef,
                                                 const float* __restrict__ x,
                                                 const float* __restrict__ WOh,
                                                 const float* __restrict__ bOh) {
    __shared__ float sW[4096];
    __shared__ float ssum[64], ssq[64];
    int tid = threadIdx.x;
    for (int i = tid; i < 4096; i += 256) sW[i] = WOh[i];
    if (tid < 64) { ssum[tid] = 0.f; ssq[tid] = 0.f; }
    __syncthreads();

    int l = tid & 31;
    int n = blockIdx.x * 8 + (tid >> 5);
    if (n < NN) {
        int start = d_rowoff[n], end = d_rowoff[n + 1];
        int h0 = l >> 3;
        float accV0 = 0.f, accV1 = 0.f, accR0 = 0.f, accR1 = 0.f, den0 = 0.f, den1 = 0.f;
        for (int j = start; j < end; j += 32) {
            int m = end - j; if (m > 32) m = 32;
            int e_l = 0, s_l = 0;
            if (l < m) { e_l = __ldg(&d_col[j + l]); s_l = __ldg(&eidx[e_l]); }
#pragma unroll 2
            for (int t = 0; t < m; t++) {
                int e = __shfl_sync(FULLM, e_l, t);
                int src = __shfl_sync(FULLM, s_l, t);
                float ex0 = __expf(__ldg(&d_scoreb[(size_t)e * 8 + h0]));
                float ex1 = __expf(__ldg(&d_scoreb[(size_t)e * 8 + h0 + 4]));
                den0 += ex0; den1 += ex1;
                accV0 += __ldg(&d_V[(size_t)src * 64 + l]) * ex0;
                accV1 += __ldg(&d_V[(size_t)src * 64 + 32 + l]) * ex1;
                accR0 += __ldg(&d_sbuf[(size_t)e * 64 + l]) * ex0;
                accR1 += __ldg(&d_sbuf[(size_t)e * 64 + 32 + l]) * ex1;
            }
        }
        float inv0 = 1.f / (den0 + 1e-16f), inv1 = 1.f / (den1 + 1e-16f);
        float rv0 = accR0 * inv0, rv1 = accR1 * inv1;
        float out0 = accV0 * inv0, out1 = accV1 * inv1;

        int gbase = l & 24;
#pragma unroll
        for (int k = 0; k < 8; k++) {
            float r0 = __shfl_sync(FULLM, rv0, gbase + k);
            float r1 = __shfl_sync(FULLM, rv1, gbase + k);
            out0 += r0 * VeRow[k * 64 + l];
            out1 += r1 * VeRow[k * 64 + l + 32];
        }
        float deg = (float)(end - start);
        float ld = logf(deg + 1.f);
        out0 *= (dcoef[l * 2] + ld * dcoef[l * 2 + 1]);
        out1 *= (dcoef[(l + 32) * 2] + ld * dcoef[(l + 32) * 2 + 1]);

        // t1 = x + out @ WOh + bOh (out lives in warp registers)
        float a0 = bOh[l] + x[n * 64 + l];
        float a1 = bOh[l + 32] + x[n * 64 + 32 + l];
#pragma unroll
        for (int d = 0; d < 32; d++) {
            float v = __shfl_sync(FULLM, out0, d);
            a0 += v * sW[d * 64 + l];
            a1 += v * sW[d * 64 + 32 + l];
        }
#pragma unroll
        for (int d = 0; d < 32; d++) {
            float v = __shfl_sync(FULLM, out1, d);
            a0 += v * sW[(d + 32) * 64 + l];
            a1 += v * sW[(d + 32) * 64 + 32 + l];
        }
        d_t1[n * 64 + l] = a0;
        d_t1[n * 64 + 32 + l] = a1;
        atomicAdd(&ssum[l], a0);
        atomicAdd(&ssq[l], a0 * a0);
        atomicAdd(&ssum[l + 32], a1);
        atomicAdd(&ssq[l + 32], a1 * a1);
    }
    __syncthreads();
    if (tid < 64) {
        atomicAdd(&d_stats[128 + tid], ssum[tid]);
        atomicAdd(&d_stats[192 + tid], ssq[tid]);
    }
}

// ---------------- fused MLP: BN1h apply + W1/relu + W2 + residual + BN2h stats
__global__ void __launch_bounds__(256) k_mlp(const float* __restrict__ g1h,
                                             const float* __restrict__ be1h,
                                             const float* __restrict__ W1,
                                             const float* __restrict__ b1v,
                                             const float* __restrict__ W2,
                                             const float* __restrict__ b2v) {
    __shared__ float sW1[8192];
    __shared__ float sW2[8192];
    __shared__ float ssum[64], ssq[64];
    int tid = threadIdx.x;
    for (int i = tid; i < 8192; i += 256) { sW1[i] = W1[i]; sW2[i] = W2[i]; }
    if (tid < 64) { ssum[tid] = 0.f; ssq[tid] = 0.f; }
    __syncthreads();

    int l = tid & 31, w = tid >> 5;
    float mu0 = d_stats[128 + l] / NN;
    float mu1 = d_stats[160 + l] / NN;
    float var0 = d_stats[192 + l] / NN - mu0 * mu0;
    float var1 = d_stats[224 + l] / NN - mu1 * mu1;
    float sc0 = g1h[l] * rsqrtf(var0 + 1e-5f);
    float sc1 = g1h[l + 32] * rsqrtf(var1 + 1e-5f);
    float sh0 = be1h[l] - mu0 * sc0;
    float sh1 = be1h[l + 32] - mu1 * sc1;
    float bb0 = b1v[l], bb1 = b1v[l + 32], bb2 = b1v[l + 64], bb3 = b1v[l + 96];
    float b20 = b2v[l], b21 = b2v[l + 32];

    float lsum0 = 0.f, lsum1 = 0.f, lsq0 = 0.f, lsq1 = 0.f;
    int nbase = (blockIdx.x * 8 + w) * 4;
    for (int r = 0; r < 4; r++) {
        int n = nbase + r;
        if (n >= NN) break;
        float h10 = d_t1[n * 64 + l] * sc0 + sh0;
        float h11 = d_t1[n * 64 + 32 + l] * sc1 + sh1;
        float a0 = bb0, a1 = bb1, a2 = bb2, a3 = bb3;
#pragma unroll
        for (int d = 0; d < 32; d++) {
            float v = __shfl_sync(FULLM, h10, d);
            a0 += v * sW1[d * 128 + l];
            a1 += v * sW1[d * 128 + l + 32];
            a2 += v * sW1[d * 128 + l + 64];
            a3 += v * sW1[d * 128 + l + 96];
        }
#pragma unroll
        for (int d = 0; d < 32; d++) {
            float v = __shfl_sync(FULLM, h11, d);
            a0 += v * sW1[(d + 32) * 128 + l];
            a1 += v * sW1[(d + 32) * 128 + l + 32];
            a2 += v * sW1[(d + 32) * 128 + l + 64];
            a3 += v * sW1[(d + 32) * 128 + l + 96];
        }
        float m0 = fmaxf(a0, 0.f), m1 = fmaxf(a1, 0.f);
        float m2 = fmaxf(a2, 0.f), m3 = fmaxf(a3, 0.f);
        float f0 = b20, f1 = b21;
#pragma unroll
        for (int mm = 0; mm < 32; mm++) {
            float v = __shfl_sync(FULLM, m0, mm);
            f0 += v * sW2[mm * 64 + l];
            f1 += v * sW2[mm * 64 + 32 + l];
        }
#pragma unroll
        for (int mm = 0; mm < 32; mm++) {
            float v = __shfl_sync(FULLM, m1, mm);
            f0 += v * sW2[(mm + 32) * 64 + l];
            f1 += v * sW2[(mm + 32) * 64 + 32 + l];
        }
#pragma unroll
        for (int mm = 0; mm < 32; mm++) {
            float v = __shfl_sync(FULLM, m2, mm);
            f0 += v * sW2[(mm + 64) * 64 + l];
            f1 += v * sW2[(mm + 64) * 64 + 32 + l];
        }
#pragma unroll
        for (int mm = 0; mm < 32; mm++) {
            float v = __shfl_sync(FULLM, m3, mm);
            f0 += v * sW2[(mm + 96) * 64 + l];
            f1 += v * sW2[(mm + 96) * 64 + 32 + l];
        }
        float t0 = h10 + f0;
        float t1v = h11 + f1;
        d_t2[n * 64 + l] = t0;
        d_t2[n * 64 + 32 + l] = t1v;
        lsum0 += t0; lsum1 += t1v; lsq0 += t0 * t0; lsq1 += t1v * t1v;
    }
    atomicAdd(&ssum[l], lsum0);
    atomicAdd(&ssq[l], lsq0);
    atomicAdd(&ssum[l + 32], lsum1);
    atomicAdd(&ssq[l + 32], lsq1);
    __syncthreads();
    if (tid < 64) {
        atomicAdd(&d_stats[256 + tid], ssum[tid]);
        atomicAdd(&d_stats[320 + tid], ssq[tid]);
    }
}

// ---------------- final h output ----------------
__global__ void k_hout(const float* __restrict__ g2h,
                       const float* __restrict__ b2h, float* __restrict__ out) {
    int idx0 = blockIdx.x * blockDim.x + threadIdx.x;
    int stride = gridDim.x * blockDim.x;
    int col = idx0 & 63;
    float mu = d_stats[256 + col] / NN;
    float var = d_stats[320 + col] / NN - mu * mu;
    float sc = g2h[col] * rsqrtf(var + 1e-5f);
    float sh = b2h[col] - mu * sc;
    for (int i = idx0; i < NN * 64; i += stride) out[i] = d_t2[i] * sc + sh;
}

// ---------------- final e output ----------------
__global__ void k_eout(const float* __restrict__ g1e,
                       const float* __restrict__ b1e, float* __restrict__ out) {
    int idx0 = blockIdx.x * blockDim.x + threadIdx.x;
    int stride = gridDim.x * blockDim.x;
    int cg = (idx0 & 15) * 4;
    float4 sc, sh;
    {
        float mu, var, s;
        mu = d_stats[cg + 0] / NE; var = d_stats[64 + cg + 0] / NE - mu * mu;
        s = g1e[cg + 0] * rsqrtf(var + 1e-5f); sc.x = s; sh.x = b1e[cg + 0] - mu * s;
        mu = d_stats[cg + 1] / NE; var = d_stats[64 + cg + 1] / NE - mu * mu;
        s = g1e[cg + 1] * rsqrtf(var + 1e-5f); sc.y = s; sh.y = b1e[cg + 1] - mu * s;
        mu = d_stats[cg + 2] / NE; var = d_stats[64 + cg + 2] / NE - mu * mu;
        s = g1e[cg + 2] * rsqrtf(var + 1e-5f); sc.z = s; sh.z = b1e[cg + 2] - mu * s;
        mu = d_stats[cg + 3] / NE; var = d_stats[64 + cg + 3] / NE - mu * mu;
        s = g1e[cg + 3] * rsqrtf(var + 1e-5f); sc.w = s; sh.w = b1e[cg + 3] - mu * s;
    }
    const float4* in = (const float4*)d_epre;
    float4* o = (float4*)out;
    const int total = NE * 16;
    for (int i = idx0; i < total; i += stride) {
        float4 v = in[i];
        v.x = v.x * sc.x + sh.x;
        v.y = v.y * sc.y + sh.y;
        v.z = v.z * sc.z + sh.z;
        v.w = v.w * sc.w + sh.w;
        o[i] = v;
    }
}

// ---------------- launch ----------------
extern "C" void kernel_launch(void* const* d_in, const int* in_sizes, int n_in,
                              void* d_out, int out_size) {
    const float* x     = (const float*)d_in[0];
    const float* ea    = (const float*)d_in[1];
    const int*   eidx  = (const int*)d_in[2];
    const float* Wq    = (const float*)d_in[3];
    const float* bq    = (const float*)d_in[4];
    const float* Wk    = (const float*)d_in[5];
    const float* We    = (const float*)d_in[6];
    const float* be    = (const float*)d_in[7];
    const float* Wv    = (const float*)d_in[8];
    const float* Aw    = (const float*)d_in[9];
    const float* VeRow = (const float*)d_in[10];
    const float* dcoef = (const float*)d_in[11];
    const float* WOh   = (const float*)d_in[12];
    const float* bOh   = (const float*)d_in[13];
    const float* WOe   = (const float*)d_in[14];
    const float* bOe   = (const float*)d_in[15];
    const float* g1h   = (const float*)d_in[16];
    const float* b1h   = (const float*)d_in[17];
    const float* g1e   = (const float*)d_in[18];
    const float* b1e   = (const float*)d_in[19];
    const float* W1    = (const float*)d_in[20];
    const float* b1v   = (const float*)d_in[21];
    const float* W2    = (const float*)d_in[22];
    const float* b2v   = (const float*)d_in[23];
    const float* g2h   = (const float*)d_in[24];
    const float* b2h   = (const float*)d_in[25];
    float* out = (float*)d_out;

    const int edge_smem = (21760 + 128) * 4;
    cudaFuncSetAttribute(k_edge_mma, cudaFuncAttributeMaxDynamicSharedMemorySize, edge_smem);

    k_zero<<<196, 256>>>();
    k_count<<<3125, 256>>>(eidx);
    k_scan<<<1, 1024>>>();
    k_fill<<<3125, 256>>>(eidx);
    k_qkv<<<1563, 256>>>(x, Wq, bq, Wk, Wv);
    k_edge_mma<<<6250, 256, edge_smem>>>(ea, eidx, We, be, Aw, WOe, bOe);
    k_node_h1<<<6250, 256>>>(eidx, VeRow, dcoef, x, WOh, bOh);
    k_mlp<<<1563, 256>>>(g1h, b1h, W1, b1v, W2, b2v);
    k_hout<<<512, 256>>>(g2h, b2h, out);
    k_eout<<<4096, 256>>>(g1e, b1e, out + (size_t)NN * 64);
}

// round 4
// speedup vs baseline: 1.3545x; 1.3545x over previous
#include <cuda_runtime.h>
#include <math.h>

#define NN 50000
#define NE 800000
#define NTILES 6250
#define FULLM 0xffffffffu

// ---------------- device scratch ----------------
__device__ float    d_Q[NN * 64];
__device__ float    d_K[NN * 64];
__device__ float    d_V[NN * 64];
__device__ unsigned d_sbufp[NE * 32];   // bf16x2-packed s
__device__ float    d_scoreb[NE * 8];
__device__ float    d_epre[NE * 64];
__device__ float    d_t1[NN * 64];
__device__ float    d_t2[NN * 64];
__device__ int      d_rowoff[NN + 1];
__device__ int      d_counts[NN];
__device__ int      d_cursor[NN];
__device__ int      d_col[NE];
__device__ float    d_stats[384];

__device__ __forceinline__ unsigned cvt_tf32(float x) {
    unsigned r;
    asm("cvt.rna.tf32.f32 %0, %1;" : "=r"(r) : "f"(x));
    return r;
}

#define MMA_TF32(C, A0, A1, A2, A3, B0, B1)                                   \
    asm volatile(                                                             \
        "mma.sync.aligned.m16n8k8.row.col.f32.tf32.tf32.f32 "                 \
        "{%0,%1,%2,%3}, {%4,%5,%6,%7}, {%8,%9}, {%0,%1,%2,%3};"               \
        : "+f"(C[0]), "+f"(C[1]), "+f"(C[2]), "+f"(C[3])                      \
        : "r"(A0), "r"(A1), "r"(A2), "r"(A3), "r"(B0), "r"(B1))

// ---------------- zero ----------------
__global__ void k_zero() {
    int i = blockIdx.x * blockDim.x + threadIdx.x;
    if (i < NN) d_counts[i] = 0;
    if (i < 384) d_stats[i] = 0.f;
}

// ---------------- CSR build ----------------
__global__ void k_count(const int* __restrict__ eidx) {
    int e = blockIdx.x * blockDim.x + threadIdx.x;
    if (e < NE) atomicAdd(&d_counts[eidx[NE + e]], 1);
}

__global__ void k_scan() {
    __shared__ int sh[1024];
    int tid = threadIdx.x;
    const int per = (NN + 1023) / 1024;
    int s = tid * per;
    int e = s + per; if (e > NN) e = NN;
    int sum = 0;
    for (int i = s; i < e && i < NN; i++) sum += d_counts[i];
    sh[tid] = sum;
    __syncthreads();
    for (int off = 1; off < 1024; off <<= 1) {
        int t = (tid >= off) ? sh[tid - off] : 0;
        __syncthreads();
        sh[tid] += t;
        __syncthreads();
    }
    int run = sh[tid] - sum;
    for (int i = s; i < e && i < NN; i++) {
        d_rowoff[i] = run;
        d_cursor[i] = run;
        run += d_counts[i];
    }
    if (tid == 1023) d_rowoff[NN] = sh[1023];
}

__global__ void k_fill(const int* __restrict__ eidx) {
    int e = blockIdx.x * blockDim.x + threadIdx.x;
    if (e < NE) {
        int dst = eidx[NE + e];
        int p = atomicAdd(&d_cursor[dst], 1);
        d_col[p] = e;
    }
}

// ---------------- Q,K,V node GEMM ----------------
__global__ void __launch_bounds__(256) k_qkv(const float* __restrict__ x,
                                             const float* __restrict__ Wq,
                                             const float* __restrict__ bq,
                                             const float* __restrict__ Wk,
                                             const float* __restrict__ Wv) {
    __shared__ float sWq[4096], sWk[4096], sWv[4096];
    int tid = threadIdx.x;
    for (int i = tid; i < 4096; i += 256) { sWq[i] = Wq[i]; sWk[i] = Wk[i]; sWv[i] = Wv[i]; }
    __syncthreads();
    int l = tid & 31, w = tid >> 5;
    float bq0 = bq[l], bq1 = bq[l + 32];
    int nbase = (blockIdx.x * 8 + w) * 4;
    for (int r = 0; r < 4; r++) {
        int n = nbase + r;
        if (n >= NN) break;
        float x0 = x[n * 64 + l], x1 = x[n * 64 + 32 + l];
        float q0 = bq0, q1 = bq1, k0 = 0.f, k1 = 0.f, v0 = 0.f, v1 = 0.f;
#pragma unroll
        for (int d = 0; d < 32; d++) {
            float xv = __shfl_sync(FULLM, x0, d);
            q0 += xv * sWq[d * 64 + l]; q1 += xv * sWq[d * 64 + 32 + l];
            k0 += xv * sWk[d * 64 + l]; k1 += xv * sWk[d * 64 + 32 + l];
            v0 += xv * sWv[d * 64 + l]; v1 += xv * sWv[d * 64 + 32 + l];
        }
#pragma unroll
        for (int d = 0; d < 32; d++) {
            float xv = __shfl_sync(FULLM, x1, d);
            q0 += xv * sWq[(d + 32) * 64 + l]; q1 += xv * sWq[(d + 32) * 64 + 32 + l];
            k0 += xv * sWk[(d + 32) * 64 + l]; k1 += xv * sWk[(d + 32) * 64 + 32 + l];
            v0 += xv * sWv[(d + 32) * 64 + l]; v1 += xv * sWv[(d + 32) * 64 + 32 + l];
        }
        d_Q[n * 64 + l] = q0; d_Q[n * 64 + 32 + l] = q1;
        d_K[n * 64 + l] = k0; d_K[n * 64 + 32 + l] = k1;
        d_V[n * 64 + l] = v0; d_V[n * 64 + 32 + l] = v1;
    }
}

// ---------------- persistent edge kernel: tf32 mma + cp.async pipeline ------
// smem layout (floats): sWeT[8704] @0, sWOeT[4352] @8704, sStats[128] @13056,
//                       sA buffers @13184 and @21888 (each 128x68)
__device__ __forceinline__ void prefetch_tile(float* dst, const float* src, int tid) {
#pragma unroll
    for (int i = tid; i < 2048; i += 256) {
        int r = i >> 4, c4 = (i & 15) << 2;
        unsigned daddr = (unsigned)__cvta_generic_to_shared(dst + r * 68 + c4);
        asm volatile("cp.async.cg.shared.global [%0], [%1], 16;"
                     :: "r"(daddr), "l"(src + r * 64 + c4));
    }
}

__global__ void __launch_bounds__(256) k_edge_mma(const float* __restrict__ ea,
                                                  const int* __restrict__ eidx,
                                                  const float* __restrict__ We,
                                                  const float* __restrict__ be,
                                                  const float* __restrict__ Aw,
                                                  const float* __restrict__ WOe,
                                                  const float* __restrict__ bOe) {
    extern __shared__ float smem[];
    float* sWeT   = smem;
    float* sWOeT  = smem + 8704;
    float* sStats = smem + 13056;
    float* sAbuf[2] = { smem + 13184, smem + 21888 };

    const int tid = threadIdx.x;

    if (tid < 128) sStats[tid] = 0.f;
    for (int i = tid; i < 8192; i += 256) {
        int k = i >> 7, n = i & 127;
        int t7 = k & 7;
        int kd = (k & ~7) + ((t7 & 3) << 1) + (t7 >> 2);
        sWeT[n * 68 + kd] = __uint_as_float(cvt_tf32(We[i]));
    }
    for (int i = tid; i < 4096; i += 256) {
        int k = i >> 6, n = i & 63;
        int t7 = k & 7;
        int kd = (k & ~7) + ((t7 & 3) << 1) + (t7 >> 2);
        sWOeT[n * 68 + kd] = __uint_as_float(cvt_tf32(WOe[i]));
    }

    const int l = tid & 31;
    const int w16 = (tid >> 5) * 16;
    const int g = l >> 2, tig = l & 3;
    const int rA0 = (w16 + g) * 68;
    const int rA1 = rA0 + 8 * 68;

    // per-lane constants hoisted out of the tile loop
    float bo0c = __ldg(&bOe[2 * tig]);      // used at col = nt*8 + 2*tig
    // (bOe varies per nt; load per nt below instead)
    (void)bo0c;

    int tile = blockIdx.x;
    int cur = 0;
    if (tile < NTILES) {
        prefetch_tile(sAbuf[0], ea + (size_t)tile * 8192, tid);
        asm volatile("cp.async.commit_group;");
    }

    for (; tile < NTILES; tile += gridDim.x) {
        asm volatile("cp.async.wait_group 0;");
        __syncthreads();
        int next = tile + gridDim.x;
        if (next < NTILES) {
            prefetch_tile(sAbuf[cur ^ 1], ea + (size_t)next * 8192, tid);
            asm volatile("cp.async.commit_group;");
        }
        float* sA = sAbuf[cur];
        const int tileBase = tile * 128;

        // ---- GEMM1 ----
        float c1[16][4];
#pragma unroll
        for (int nt = 0; nt < 16; nt++)
#pragma unroll
            for (int s = 0; s < 4; s++) c1[nt][s] = 0.f;

#pragma unroll
        for (int ks = 0; ks < 8; ks++) {
            unsigned a0 = cvt_tf32(sA[rA0 + ks * 8 + tig]);
            unsigned a1 = cvt_tf32(sA[rA1 + ks * 8 + tig]);
            unsigned a2 = cvt_tf32(sA[rA0 + ks * 8 + tig + 4]);
            unsigned a3 = cvt_tf32(sA[rA1 + ks * 8 + tig + 4]);
#pragma unroll
            for (int nt = 0; nt < 16; nt++) {
                float2 bb = *(const float2*)&sWeT[(nt * 8 + g) * 68 + ks * 8 + 2 * tig];
                MMA_TF32(c1[nt], a0, a1, a2, a3, __float_as_uint(bb.x), __float_as_uint(bb.y));
            }
        }

        // ---- init C2 with ea + bOe ----
        float c2[8][4];
#pragma unroll
        for (int nt = 0; nt < 8; nt++) {
            int col = nt * 8 + 2 * tig;
            float2 e0v = *(const float2*)&sA[rA0 + col];
            float2 e1v = *(const float2*)&sA[rA1 + col];
            float bo0 = __ldg(&bOe[col]), bo1 = __ldg(&bOe[col + 1]);
            c2[nt][0] = e0v.x + bo0; c2[nt][1] = e0v.y + bo1;
            c2[nt][2] = e1v.x + bo0; c2[nt][3] = e1v.y + bo1;
        }
        __syncwarp();

        // ---- epilogue 1 ----
        const int e0 = tileBase + w16 + g;
        const int e1 = e0 + 8;
        int src0 = __ldg(&eidx[e0]), dst0 = __ldg(&eidx[NE + e0]);
        int src1 = __ldg(&eidx[e1]), dst1 = __ldg(&eidx[NE + e1]);
        const float* K0 = d_K + (size_t)src0 * 64;
        const float* Q0 = d_Q + (size_t)dst0 * 64;
        const float* K1 = d_K + (size_t)src1 * 64;
        const float* Q1 = d_Q + (size_t)dst1 * 64;

#pragma unroll
        for (int h = 0; h < 8; h++) {
            const int nt = 2 * h;
            const int dc = h * 8 + 2 * tig;
            float2 ka = *(const float2*)(K0 + dc);
            float2 qa = *(const float2*)(Q0 + dc);
            float2 kb = *(const float2*)(K1 + dc);
            float2 qb = *(const float2*)(Q1 + dc);
            float kq00 = ka.x + qa.x, kq01 = ka.y + qa.y;
            float kq10 = kb.x + qb.x, kq11 = kb.y + qb.y;
            float bw0 = __ldg(&be[h * 16 + 2 * tig]);
            float bw1 = __ldg(&be[h * 16 + 2 * tig + 1]);
            float bb0 = __ldg(&be[h * 16 + 8 + 2 * tig]);
            float bb1 = __ldg(&be[h * 16 + 9 + 2 * tig]);
            float aw0 = __ldg(&Aw[(2 * tig) * 8 + h]);
            float aw1 = __ldg(&Aw[(2 * tig + 1) * 8 + h]);

            float t00 = kq00 * (c1[nt][0] + bw0);
            float t01 = kq01 * (c1[nt][1] + bw1);
            float t10 = kq10 * (c1[nt][2] + bw0);
            float t11 = kq11 * (c1[nt][3] + bw1);
            float s00 = fmaxf(copysignf(sqrtf(fabsf(t00)), t00) + (c1[nt + 1][0] + bb0), 0.f);
            float s01 = fmaxf(copysignf(sqrtf(fabsf(t01)), t01) + (c1[nt + 1][1] + bb1), 0.f);
            float s10 = fmaxf(copysignf(sqrtf(fabsf(t10)), t10) + (c1[nt + 1][2] + bb0), 0.f);
            float s11 = fmaxf(copysignf(sqrtf(fabsf(t11)), t11) + (c1[nt + 1][3] + bb1), 0.f);

            unsigned pk0, pk1;
            asm("cvt.rn.bf16x2.f32 %0, %1, %2;" : "=r"(pk0) : "f"(s01), "f"(s00));
            asm("cvt.rn.bf16x2.f32 %0, %1, %2;" : "=r"(pk1) : "f"(s11), "f"(s10));
            d_sbufp[(size_t)e0 * 32 + h * 4 + tig] = pk0;
            d_sbufp[(size_t)e1 * 32 + h * 4 + tig] = pk1;
            *(float2*)&sA[rA0 + dc] = make_float2(s00, s01);
            *(float2*)&sA[rA1 + dc] = make_float2(s10, s11);

            float p0 = s00 * aw0 + s01 * aw1;
            float p1 = s10 * aw0 + s11 * aw1;
            p0 += __shfl_xor_sync(FULLM, p0, 1);
            p0 += __shfl_xor_sync(FULLM, p0, 2);
            p1 += __shfl_xor_sync(FULLM, p1, 1);
            p1 += __shfl_xor_sync(FULLM, p1, 2);
            if (tig == 0) {
                d_scoreb[(size_t)e0 * 8 + h] = fminf(fmaxf(p0, -5.f), 5.f);
                d_scoreb[(size_t)e1 * 8 + h] = fminf(fmaxf(p1, -5.f), 5.f);
            }
        }
        __syncwarp();

        // ---- GEMM2 ----
#pragma unroll
        for (int ks = 0; ks < 8; ks++) {
            unsigned a0 = cvt_tf32(sA[rA0 + ks * 8 + tig]);
            unsigned a1 = cvt_tf32(sA[rA1 + ks * 8 + tig]);
            unsigned a2 = cvt_tf32(sA[rA0 + ks * 8 + tig + 4]);
            unsigned a3 = cvt_tf32(sA[rA1 + ks * 8 + tig + 4]);
#pragma unroll
            for (int nt = 0; nt < 8; nt++) {
                float2 bb = *(const float2*)&sWOeT[(nt * 8 + g) * 68 + ks * 8 + 2 * tig];
                MMA_TF32(c2[nt], a0, a1, a2, a3, __float_as_uint(bb.x), __float_as_uint(bb.y));
            }
        }

        // ---- epilogue 2 ----
#pragma unroll
        for (int nt = 0; nt < 8; nt++) {
            int col = nt * 8 + 2 * tig;
            *(float2*)&d_epre[(size_t)e0 * 64 + col] = make_float2(c2[nt][0], c2[nt][1]);
            *(float2*)&d_epre[(size_t)e1 * 64 + col] = make_float2(c2[nt][2], c2[nt][3]);
            float s0 = c2[nt][0] + c2[nt][2];
            float s1 = c2[nt][1] + c2[nt][3];
            float q0 = c2[nt][0] * c2[nt][0] + c2[nt][2] * c2[nt][2];
            float q1 = c2[nt][1] * c2[nt][1] + c2[nt][3] * c2[nt][3];
#pragma unroll
            for (int off = 4; off < 32; off <<= 1) {
                s0 += __shfl_xor_sync(FULLM, s0, off);
                s1 += __shfl_xor_sync(FULLM, s1, off);
                q0 += __shfl_xor_sync(FULLM, q0, off);
                q1 += __shfl_xor_sync(FULLM, q1, off);
            }
            if (l < 4) {
                atomicAdd(&sStats[col], s0);
                atomicAdd(&sStats[col + 1], s1);
                atomicAdd(&sStats[64 + col], q0);
                atomicAdd(&sStats[64 + col + 1], q1);
            }
        }
        cur ^= 1;
        __syncthreads();
    }

    __syncthreads();
    if (tid < 64) {
        atomicAdd(&d_stats[tid], sStats[tid]);
        atomicAdd(&d_stats[64 + tid], sStats[64 + tid]);
    }
}

// ---------------- fused node kernel: attention gather + WOh GEMM + BN1h stats
__global__ void __launch_bounds__(256) k_node_h1(const int* __restrict__ eidx,
                                                 const float* __restrict__ VeRow,
                                                 const float* __restrict__ dcoef,
                                                 const float* __restrict__ x,
                                                 const float* __restrict__ WOh,
                                                 const float* __restrict__ bOh) {
    __shared__ float sW[4096];
    __shared__ float ssum[64], ssq[64];
    int tid = threadIdx.x;
    for (int i = tid; i < 4096; i += 256) sW[i] = WOh[i];
    if (tid < 64) { ssum[tid] = 0.f; ssq[tid] = 0.f; }
    __syncthreads();

    int l = tid & 31;
    int n = blockIdx.x * 8 + (tid >> 5);
    if (n < NN) {
        int start = d_rowoff[n], end = d_rowoff[n + 1];
        int h0 = l >> 3;
        int wsel = l >> 1;
        unsigned shift = (l & 1) ? 0u : 16u;  // odd lane: hi half; even: lo half (<<16)
        float accV0 = 0.f, accV1 = 0.f, accR0 = 0.f, accR1 = 0.f, den0 = 0.f, den1 = 0.f;
        for (int j = start; j < end; j += 32) {
            int m = end - j; if (m > 32) m = 32;
            int e_l = 0, s_l = 0;
            if (l < m) { e_l = __ldg(&d_col[j + l]); s_l = __ldg(&eidx[e_l]); }
#pragma unroll 2
            for (int t = 0; t < m; t++) {
                int e = __shfl_sync(FULLM, e_l, t);
                int src = __shfl_sync(FULLM, s_l, t);
                float ex0 = __expf(__ldg(&d_scoreb[(size_t)e * 8 + h0]));
                float ex1 = __expf(__ldg(&d_scoreb[(size_t)e * 8 + h0 + 4]));
                den0 += ex0; den1 += ex1;
                accV0 += __ldg(&d_V[(size_t)src * 64 + l]) * ex0;
                accV1 += __ldg(&d_V[(size_t)src * 64 + 32 + l]) * ex1;
                unsigned wlo = __ldg(&d_sbufp[(size_t)e * 32 + wsel]);
                unsigned whi = __ldg(&d_sbufp[(size_t)e * 32 + 16 + wsel]);
                float sb0 = __uint_as_float((l & 1) ? (wlo & 0xffff0000u) : (wlo << shift));
                float sb1 = __uint_as_float((l & 1) ? (whi & 0xffff0000u) : (whi << shift));
                accR0 += sb0 * ex0;
                accR1 += sb1 * ex1;
            }
        }
        float inv0 = 1.f / (den0 + 1e-16f), inv1 = 1.f / (den1 + 1e-16f);
        float rv0 = accR0 * inv0, rv1 = accR1 * inv1;
        float out0 = accV0 * inv0, out1 = accV1 * inv1;

        int gbase = l & 24;
#pragma unroll
        for (int k = 0; k < 8; k++) {
            float r0 = __shfl_sync(FULLM, rv0, gbase + k);
            float r1 = __shfl_sync(FULLM, rv1, gbase + k);
            out0 += r0 * VeRow[k * 64 + l];
            out1 += r1 * VeRow[k * 64 + l + 32];
        }
        float deg = (float)(end - start);
        float ld = logf(deg + 1.f);
        out0 *= (dcoef[l * 2] + ld * dcoef[l * 2 + 1]);
        out1 *= (dcoef[(l + 32) * 2] + ld * dcoef[(l + 32) * 2 + 1]);

        float a0 = bOh[l] + x[n * 64 + l];
        float a1 = bOh[l + 32] + x[n * 64 + 32 + l];
#pragma unroll
        for (int d = 0; d < 32; d++) {
            float v = __shfl_sync(FULLM, out0, d);
            a0 += v * sW[d * 64 + l];
            a1 += v * sW[d * 64 + 32 + l];
        }
#pragma unroll
        for (int d = 0; d < 32; d++) {
            float v = __shfl_sync(FULLM, out1, d);
            a0 += v * sW[(d + 32) * 64 + l];
            a1 += v * sW[(d + 32) * 64 + 32 + l];
        }
        d_t1[n * 64 + l] = a0;
        d_t1[n * 64 + 32 + l] = a1;
        atomicAdd(&ssum[l], a0);
        atomicAdd(&ssq[l], a0 * a0);
        atomicAdd(&ssum[l + 32], a1);
        atomicAdd(&ssq[l + 32], a1 * a1);
    }
    __syncthreads();
    if (tid < 64) {
        atomicAdd(&d_stats[128 + tid], ssum[tid]);
        atomicAdd(&d_stats[192 + tid], ssq[tid]);
    }
}

// ---------------- fused MLP ----------------
__global__ void __launch_bounds__(256) k_mlp(const float* __restrict__ g1h,
                                             const float* __restrict__ be1h,
                                             const float* __restrict__ W1,
                                             const float* __restrict__ b1v,
                                             const float* __restrict__ W2,
                                             const float* __restrict__ b2v) {
    __shared__ float sW1[8192];
    __shared__ float sW2[8192];
    __shared__ float ssum[64], ssq[64];
    int tid = threadIdx.x;
    for (int i = tid; i < 8192; i += 256) { sW1[i] = W1[i]; sW2[i] = W2[i]; }
    if (tid < 64) { ssum[tid] = 0.f; ssq[tid] = 0.f; }
    __syncthreads();

    int l = tid & 31, w = tid >> 5;
    float mu0 = d_stats[128 + l] / NN;
    float mu1 = d_stats[160 + l] / NN;
    float var0 = d_stats[192 + l] / NN - mu0 * mu0;
    float var1 = d_stats[224 + l] / NN - mu1 * mu1;
    float sc0 = g1h[l] * rsqrtf(var0 + 1e-5f);
    float sc1 = g1h[l + 32] * rsqrtf(var1 + 1e-5f);
    float sh0 = be1h[l] - mu0 * sc0;
    float sh1 = be1h[l + 32] - mu1 * sc1;
    float bb0 = b1v[l], bb1 = b1v[l + 32], bb2 = b1v[l + 64], bb3 = b1v[l + 96];
    float b20 = b2v[l], b21 = b2v[l + 32];

    float lsum0 = 0.f, lsum1 = 0.f, lsq0 = 0.f, lsq1 = 0.f;
    int nbase = (blockIdx.x * 8 + w) * 4;
    for (int r = 0; r < 4; r++) {
        int n = nbase + r;
        if (n >= NN) break;
        float h10 = d_t1[n * 64 + l] * sc0 + sh0;
        float h11 = d_t1[n * 64 + 32 + l] * sc1 + sh1;
        float a0 = bb0, a1 = bb1, a2 = bb2, a3 = bb3;
#pragma unroll
        for (int d = 0; d < 32; d++) {
            float v = __shfl_sync(FULLM, h10, d);
            a0 += v * sW1[d * 128 + l];
            a1 += v * sW1[d * 128 + l + 32];
            a2 += v * sW1[d * 128 + l + 64];
            a3 += v * sW1[d * 128 + l + 96];
        }
#pragma unroll
        for (int d = 0; d < 32; d++) {
            float v = __shfl_sync(FULLM, h11, d);
            a0 += v * sW1[(d + 32) * 128 + l];
            a1 += v * sW1[(d + 32) * 128 + l + 32];
            a2 += v * sW1[(d + 32) * 128 + l + 64];
            a3 += v * sW1[(d + 32) * 128 + l + 96];
        }
        float m0 = fmaxf(a0, 0.f), m1 = fmaxf(a1, 0.f);
        float m2 = fmaxf(a2, 0.f), m3 = fmaxf(a3, 0.f);
        float f0 = b20, f1 = b21;
#pragma unroll
        for (int mm = 0; mm < 32; mm++) {
            float v = __shfl_sync(FULLM, m0, mm);
            f0 += v * sW2[mm * 64 + l];
            f1 += v * sW2[mm * 64 + 32 + l];
        }
#pragma unroll
        for (int mm = 0; mm < 32; mm++) {
            float v = __shfl_sync(FULLM, m1, mm);
            f0 += v * sW2[(mm + 32) * 64 + l];
            f1 += v * sW2[(mm + 32) * 64 + 32 + l];
        }
#pragma unroll
        for (int mm = 0; mm < 32; mm++) {
            float v = __shfl_sync(FULLM, m2, mm);
            f0 += v * sW2[(mm + 64) * 64 + l];
            f1 += v * sW2[(mm + 64) * 64 + 32 + l];
        }
#pragma unroll
        for (int mm = 0; mm < 32; mm++) {
            float v = __shfl_sync(FULLM, m3, mm);
            f0 += v * sW2[(mm + 96) * 64 + l];
            f1 += v * sW2[(mm + 96) * 64 + 32 + l];
        }
        float t0 = h10 + f0;
        float t1v = h11 + f1;
        d_t2[n * 64 + l] = t0;
        d_t2[n * 64 + 32 + l] = t1v;
        lsum0 += t0; lsum1 += t1v; lsq0 += t0 * t0; lsq1 += t1v * t1v;
    }
    atomicAdd(&ssum[l], lsum0);
    atomicAdd(&ssq[l], lsq0);
    atomicAdd(&ssum[l + 32], lsum1);
    atomicAdd(&ssq[l + 32], lsq1);
    __syncthreads();
    if (tid < 64) {
        atomicAdd(&d_stats[256 + tid], ssum[tid]);
        atomicAdd(&d_stats[320 + tid], ssq[tid]);
    }
}

// ---------------- final h output ----------------
__global__ void k_hout(const float* __restrict__ g2h,
                       const float* __restrict__ b2h, float* __restrict__ out) {
    int idx0 = blockIdx.x * blockDim.x + threadIdx.x;
    int stride = gridDim.x * blockDim.x;
    int col = idx0 & 63;
    float mu = d_stats[256 + col] / NN;
    float var = d_stats[320 + col] / NN - mu * mu;
    float sc = g2h[col] * rsqrtf(var + 1e-5f);
    float sh = b2h[col] - mu * sc;
    for (int i = idx0; i < NN * 64; i += stride) out[i] = d_t2[i] * sc + sh;
}

// ---------------- final e output ----------------
__global__ void k_eout(const float* __restrict__ g1e,
                       const float* __restrict__ b1e, float* __restrict__ out) {
    int idx0 = blockIdx.x * blockDim.x + threadIdx.x;
    int stride = gridDim.x * blockDim.x;
    int cg = (idx0 & 15) * 4;
    float4 sc, sh;
    {
        float mu, var, s;
        mu = d_stats[cg + 0] / NE; var = d_stats[64 + cg + 0] / NE - mu * mu;
        s = g1e[cg + 0] * rsqrtf(var + 1e-5f); sc.x = s; sh.x = b1e[cg + 0] - mu * s;
        mu = d_stats[cg + 1] / NE; var = d_stats[64 + cg + 1] / NE - mu * mu;
        s = g1e[cg + 1] * rsqrtf(var + 1e-5f); sc.y = s; sh.y = b1e[cg + 1] - mu * s;
        mu = d_stats[cg + 2] / NE; var = d_stats[64 + cg + 2] / NE - mu * mu;
        s = g1e[cg + 2] * rsqrtf(var + 1e-5f); sc.z = s; sh.z = b1e[cg + 2] - mu * s;
        mu = d_stats[cg + 3] / NE; var = d_stats[64 + cg + 3] / NE - mu * mu;
        s = g1e[cg + 3] * rsqrtf(var + 1e-5f); sc.w = s; sh.w = b1e[cg + 3] - mu * s;
    }
    const float4* in = (const float4*)d_epre;
    float4* o = (float4*)out;
    const int total = NE * 16;
    for (int i = idx0; i < total; i += stride) {
        float4 v = in[i];
        v.x = v.x * sc.x + sh.x;
        v.y = v.y * sc.y + sh.y;
        v.z = v.z * sc.z + sh.z;
        v.w = v.w * sc.w + sh.w;
        o[i] = v;
    }
}

// ---------------- launch ----------------
extern "C" void kernel_launch(void* const* d_in, const int* in_sizes, int n_in,
                              void* d_out, int out_size) {
    const float* x     = (const float*)d_in[0];
    const float* ea    = (const float*)d_in[1];
    const int*   eidx  = (const int*)d_in[2];
    const float* Wq    = (const float*)d_in[3];
    const float* bq    = (const float*)d_in[4];
    const float* Wk    = (const float*)d_in[5];
    const float* We    = (const float*)d_in[6];
    const float* be    = (const float*)d_in[7];
    const float* Wv    = (const float*)d_in[8];
    const float* Aw    = (const float*)d_in[9];
    const float* VeRow = (const float*)d_in[10];
    const float* dcoef = (const float*)d_in[11];
    const float* WOh   = (const float*)d_in[12];
    const float* bOh   = (const float*)d_in[13];
    const float* WOe   = (const float*)d_in[14];
    const float* bOe   = (const float*)d_in[15];
    const float* g1h   = (const float*)d_in[16];
    const float* b1h   = (const float*)d_in[17];
    const float* g1e   = (const float*)d_in[18];
    const float* b1e   = (const float*)d_in[19];
    const float* W1    = (const float*)d_in[20];
    const float* b1v   = (const float*)d_in[21];
    const float* W2    = (const float*)d_in[22];
    const float* b2v   = (const float*)d_in[23];
    const float* g2h   = (const float*)d_in[24];
    const float* b2h   = (const float*)d_in[25];
    float* out = (float*)d_out;

    const int edge_smem = 30592 * 4;  // 122,368 B
    cudaFuncSetAttribute(k_edge_mma, cudaFuncAttributeMaxDynamicSharedMemorySize, edge_smem);

    k_zero<<<196, 256>>>();
    k_count<<<3125, 256>>>(eidx);
    k_scan<<<1, 1024>>>();
    k_fill<<<3125, 256>>>(eidx);
    k_qkv<<<1563, 256>>>(x, Wq, bq, Wk, Wv);
    k_edge_mma<<<148, 256, edge_smem>>>(ea, eidx, We, be, Aw, WOe, bOe);
    k_node_h1<<<6250, 256>>>(eidx, VeRow, dcoef, x, WOh, bOh);
    k_mlp<<<1563, 256>>>(g1h, b1h, W1, b1v, W2, b2v);
    k_hout<<<512, 256>>>(g2h, b2h, out);
    k_eout<<<4096, 256>>>(g1e, b1e, out + (size_t)NN * 64);
}

// round 5
// speedup vs baseline: 1.3838x; 1.0216x over previous
#include <cuda_runtime.h>
#include <cuda_fp16.h>
#include <math.h>

#define NN 50000
#define NE 800000
#define NTILES 6250
#define FULLM 0xffffffffu

// ---------------- device scratch ----------------
__device__ float    d_Q[NN * 64];
__device__ float    d_K[NN * 64];
__device__ float    d_V[NN * 64];
__device__ unsigned d_sbufp[NE * 32];   // bf16x2-packed s, PERMUTED (CSR order)
__device__ float    d_scoreb[NE * 8];   // PERMUTED (CSR order)
__device__ __half2  d_eprh[NE * 32];    // fp16-packed epre (edge order)
__device__ float    d_t1[NN * 64];
__device__ float    d_t2[NN * 64];
__device__ int      d_rowoff[NN + 1];
__device__ int      d_counts[NN];
__device__ int      d_cursor[NN];
__device__ int      d_perm[NE];         // edge -> CSR slot
__device__ int      d_srcp[NE];         // CSR slot -> src node
__device__ float    d_stats[384];

__device__ __forceinline__ unsigned cvt_tf32(float x) {
    unsigned r;
    asm("cvt.rna.tf32.f32 %0, %1;" : "=r"(r) : "f"(x));
    return r;
}

#define MMA_TF32(C, A0, A1, A2, A3, B0, B1)                                   \
    asm volatile(                                                             \
        "mma.sync.aligned.m16n8k8.row.col.f32.tf32.tf32.f32 "                 \
        "{%0,%1,%2,%3}, {%4,%5,%6,%7}, {%8,%9}, {%0,%1,%2,%3};"               \
        : "+f"(C[0]), "+f"(C[1]), "+f"(C[2]), "+f"(C[3])                      \
        : "r"(A0), "r"(A1), "r"(A2), "r"(A3), "r"(B0), "r"(B1))

// ---------------- zero ----------------
__global__ void k_zero() {
    int i = blockIdx.x * blockDim.x + threadIdx.x;
    if (i < NN) d_counts[i] = 0;
    if (i < 384) d_stats[i] = 0.f;
}

// ---------------- CSR build ----------------
__global__ void k_count(const int* __restrict__ eidx) {
    int e = blockIdx.x * blockDim.x + threadIdx.x;
    if (e < NE) atomicAdd(&d_counts[eidx[NE + e]], 1);
}

__global__ void k_scan() {
    __shared__ int sh[1024];
    int tid = threadIdx.x;
    const int per = (NN + 1023) / 1024;
    int s = tid * per;
    int e = s + per; if (e > NN) e = NN;
    int sum = 0;
    for (int i = s; i < e && i < NN; i++) sum += d_counts[i];
    sh[tid] = sum;
    __syncthreads();
    for (int off = 1; off < 1024; off <<= 1) {
        int t = (tid >= off) ? sh[tid - off] : 0;
        __syncthreads();
        sh[tid] += t;
        __syncthreads();
    }
    int run = sh[tid] - sum;
    for (int i = s; i < e && i < NN; i++) {
        d_rowoff[i] = run;
        d_cursor[i] = run;
        run += d_counts[i];
    }
    if (tid == 1023) d_rowoff[NN] = sh[1023];
}

__global__ void k_fill(const int* __restrict__ eidx) {
    int e = blockIdx.x * blockDim.x + threadIdx.x;
    if (e < NE) {
        int dst = eidx[NE + e];
        int p = atomicAdd(&d_cursor[dst], 1);
        d_perm[e] = p;
        d_srcp[p] = eidx[e];
    }
}

// ---------------- Q,K,V node GEMM ----------------
__global__ void __launch_bounds__(256) k_qkv(const float* __restrict__ x,
                                             const float* __restrict__ Wq,
                                             const float* __restrict__ bq,
                                             const float* __restrict__ Wk,
                                             const float* __restrict__ Wv) {
    __shared__ float sWq[4096], sWk[4096], sWv[4096];
    int tid = threadIdx.x;
    for (int i = tid; i < 4096; i += 256) { sWq[i] = Wq[i]; sWk[i] = Wk[i]; sWv[i] = Wv[i]; }
    __syncthreads();
    int l = tid & 31, w = tid >> 5;
    float bq0 = bq[l], bq1 = bq[l + 32];
    int nbase = (blockIdx.x * 8 + w) * 4;
    for (int r = 0; r < 4; r++) {
        int n = nbase + r;
        if (n >= NN) break;
        float x0 = x[n * 64 + l], x1 = x[n * 64 + 32 + l];
        float q0 = bq0, q1 = bq1, k0 = 0.f, k1 = 0.f, v0 = 0.f, v1 = 0.f;
#pragma unroll
        for (int d = 0; d < 32; d++) {
            float xv = __shfl_sync(FULLM, x0, d);
            q0 += xv * sWq[d * 64 + l]; q1 += xv * sWq[d * 64 + 32 + l];
            k0 += xv * sWk[d * 64 + l]; k1 += xv * sWk[d * 64 + 32 + l];
            v0 += xv * sWv[d * 64 + l]; v1 += xv * sWv[d * 64 + 32 + l];
        }
#pragma unroll
        for (int d = 0; d < 32; d++) {
            float xv = __shfl_sync(FULLM, x1, d);
            q0 += xv * sWq[(d + 32) * 64 + l]; q1 += xv * sWq[(d + 32) * 64 + 32 + l];
            k0 += xv * sWk[(d + 32) * 64 + l]; k1 += xv * sWk[(d + 32) * 64 + 32 + l];
            v0 += xv * sWv[(d + 32) * 64 + l]; v1 += xv * sWv[(d + 32) * 64 + 32 + l];
        }
        d_Q[n * 64 + l] = q0; d_Q[n * 64 + 32 + l] = q1;
        d_K[n * 64 + l] = k0; d_K[n * 64 + 32 + l] = k1;
        d_V[n * 64 + l] = v0; d_V[n * 64 + 32 + l] = v1;
    }
}

// ---------------- persistent edge kernel ----------------
// smem floats: sWeT[8704]@0, sWOeT[4352]@8704, sStats[128]@13056,
//              sScore[1024]@13184, sPerm[128]@14208, sA buffers @14336, @23040
__device__ __forceinline__ void prefetch_tile(float* dst, const float* src, int tid) {
#pragma unroll
    for (int i = tid; i < 2048; i += 256) {
        int r = i >> 4, c4 = (i & 15) << 2;
        unsigned daddr = (unsigned)__cvta_generic_to_shared(dst + r * 68 + c4);
        asm volatile("cp.async.cg.shared.global [%0], [%1], 16;"
                     :: "r"(daddr), "l"(src + r * 64 + c4));
    }
}

__global__ void __launch_bounds__(256) k_edge_mma(const float* __restrict__ ea,
                                                  const int* __restrict__ eidx,
                                                  const float* __restrict__ We,
                                                  const float* __restrict__ be,
                                                  const float* __restrict__ Aw,
                                                  const float* __restrict__ WOe,
                                                  const float* __restrict__ bOe) {
    extern __shared__ float smem[];
    float* sWeT   = smem;
    float* sWOeT  = smem + 8704;
    float* sStats = smem + 13056;
    float* sScore = smem + 13184;
    int*   sPermI = (int*)(smem + 14208);
    float* sAbuf[2] = { smem + 14336, smem + 23040 };

    const int tid = threadIdx.x;

    if (tid < 128) sStats[tid] = 0.f;
    for (int i = tid; i < 8192; i += 256) {
        int k = i >> 7, n = i & 127;
        int t7 = k & 7;
        int kd = (k & ~7) + ((t7 & 3) << 1) + (t7 >> 2);
        sWeT[n * 68 + kd] = __uint_as_float(cvt_tf32(We[i]));
    }
    for (int i = tid; i < 4096; i += 256) {
        int k = i >> 6, n = i & 63;
        int t7 = k & 7;
        int kd = (k & ~7) + ((t7 & 3) << 1) + (t7 >> 2);
        sWOeT[n * 68 + kd] = __uint_as_float(cvt_tf32(WOe[i]));
    }

    const int l = tid & 31;
    const int w16 = (tid >> 5) * 16;
    const int g = l >> 2, tig = l & 3;
    const int rA0 = (w16 + g) * 68;
    const int rA1 = rA0 + 8 * 68;

    int tile = blockIdx.x;
    int cur = 0;
    if (tile < NTILES) {
        prefetch_tile(sAbuf[0], ea + (size_t)tile * 8192, tid);
        asm volatile("cp.async.commit_group;");
    }

    for (; tile < NTILES; tile += gridDim.x) {
        asm volatile("cp.async.wait_group 0;");
        __syncthreads();
        const int tileBase = tile * 128;
        if (tid < 128) sPermI[tid] = d_perm[tileBase + tid];
        int next = tile + gridDim.x;
        if (next < NTILES) {
            prefetch_tile(sAbuf[cur ^ 1], ea + (size_t)next * 8192, tid);
            asm volatile("cp.async.commit_group;");
        }
        float* sA = sAbuf[cur];

        // ---- GEMM1 ----
        float c1[16][4];
#pragma unroll
        for (int nt = 0; nt < 16; nt++)
#pragma unroll
            for (int s = 0; s < 4; s++) c1[nt][s] = 0.f;

#pragma unroll
        for (int ks = 0; ks < 8; ks++) {
            unsigned a0 = cvt_tf32(sA[rA0 + ks * 8 + tig]);
            unsigned a1 = cvt_tf32(sA[rA1 + ks * 8 + tig]);
            unsigned a2 = cvt_tf32(sA[rA0 + ks * 8 + tig + 4]);
            unsigned a3 = cvt_tf32(sA[rA1 + ks * 8 + tig + 4]);
#pragma unroll
            for (int nt = 0; nt < 16; nt++) {
                float2 bb = *(const float2*)&sWeT[(nt * 8 + g) * 68 + ks * 8 + 2 * tig];
                MMA_TF32(c1[nt], a0, a1, a2, a3, __float_as_uint(bb.x), __float_as_uint(bb.y));
            }
        }

        // ---- init C2 with ea + bOe ----
        float c2[8][4];
#pragma unroll
        for (int nt = 0; nt < 8; nt++) {
            int col = nt * 8 + 2 * tig;
            float2 e0v = *(const float2*)&sA[rA0 + col];
            float2 e1v = *(const float2*)&sA[rA1 + col];
            float bo0 = __ldg(&bOe[col]), bo1 = __ldg(&bOe[col + 1]);
            c2[nt][0] = e0v.x + bo0; c2[nt][1] = e0v.y + bo1;
            c2[nt][2] = e1v.x + bo0; c2[nt][3] = e1v.y + bo1;
        }
        __syncwarp();

        // ---- epilogue 1 ----
        const int e0 = tileBase + w16 + g;
        const int e1 = e0 + 8;
        int src0 = __ldg(&eidx[e0]), dst0 = __ldg(&eidx[NE + e0]);
        int src1 = __ldg(&eidx[e1]), dst1 = __ldg(&eidx[NE + e1]);
        const float* K0 = d_K + (size_t)src0 * 64;
        const float* Q0 = d_Q + (size_t)dst0 * 64;
        const float* K1 = d_K + (size_t)src1 * 64;
        const float* Q1 = d_Q + (size_t)dst1 * 64;

#pragma unroll
        for (int h = 0; h < 8; h++) {
            const int nt = 2 * h;
            const int dc = h * 8 + 2 * tig;
            float2 ka = *(const float2*)(K0 + dc);
            float2 qa = *(const float2*)(Q0 + dc);
            float2 kb = *(const float2*)(K1 + dc);
            float2 qb = *(const float2*)(Q1 + dc);
            float kq00 = ka.x + qa.x, kq01 = ka.y + qa.y;
            float kq10 = kb.x + qb.x, kq11 = kb.y + qb.y;
            float bw0 = __ldg(&be[h * 16 + 2 * tig]);
            float bw1 = __ldg(&be[h * 16 + 2 * tig + 1]);
            float bb0 = __ldg(&be[h * 16 + 8 + 2 * tig]);
            float bb1 = __ldg(&be[h * 16 + 9 + 2 * tig]);
            float aw0 = __ldg(&Aw[(2 * tig) * 8 + h]);
            float aw1 = __ldg(&Aw[(2 * tig + 1) * 8 + h]);

            float t00 = kq00 * (c1[nt][0] + bw0);
            float t01 = kq01 * (c1[nt][1] + bw1);
            float t10 = kq10 * (c1[nt][2] + bw0);
            float t11 = kq11 * (c1[nt][3] + bw1);
            float s00 = fmaxf(copysignf(sqrtf(fabsf(t00)), t00) + (c1[nt + 1][0] + bb0), 0.f);
            float s01 = fmaxf(copysignf(sqrtf(fabsf(t01)), t01) + (c1[nt + 1][1] + bb1), 0.f);
            float s10 = fmaxf(copysignf(sqrtf(fabsf(t10)), t10) + (c1[nt + 1][2] + bb0), 0.f);
            float s11 = fmaxf(copysignf(sqrtf(fabsf(t11)), t11) + (c1[nt + 1][3] + bb1), 0.f);

            *(float2*)&sA[rA0 + dc] = make_float2(s00, s01);
            *(float2*)&sA[rA1 + dc] = make_float2(s10, s11);

            float p0 = s00 * aw0 + s01 * aw1;
            float p1 = s10 * aw0 + s11 * aw1;
            p0 += __shfl_xor_sync(FULLM, p0, 1);
            p0 += __shfl_xor_sync(FULLM, p0, 2);
            p1 += __shfl_xor_sync(FULLM, p1, 1);
            p1 += __shfl_xor_sync(FULLM, p1, 2);
            if (tig == 0) {
                sScore[(w16 + g) * 8 + h] = fminf(fmaxf(p0, -5.f), 5.f);
                sScore[(w16 + g + 8) * 8 + h] = fminf(fmaxf(p1, -5.f), 5.f);
            }
        }
        __syncwarp();

        // ---- GEMM2 ----
#pragma unroll
        for (int ks = 0; ks < 8; ks++) {
            unsigned a0 = cvt_tf32(sA[rA0 + ks * 8 + tig]);
            unsigned a1 = cvt_tf32(sA[rA1 + ks * 8 + tig]);
            unsigned a2 = cvt_tf32(sA[rA0 + ks * 8 + tig + 4]);
            unsigned a3 = cvt_tf32(sA[rA1 + ks * 8 + tig + 4]);
#pragma unroll
            for (int nt = 0; nt < 8; nt++) {
                float2 bb = *(const float2*)&sWOeT[(nt * 8 + g) * 68 + ks * 8 + 2 * tig];
                MMA_TF32(c2[nt], a0, a1, a2, a3, __float_as_uint(bb.x), __float_as_uint(bb.y));
            }
        }

        // ---- epilogue 2: epre (fp16) + BN stats ----
#pragma unroll
        for (int nt = 0; nt < 8; nt++) {
            int wi = nt * 4 + tig;
            d_eprh[(size_t)e0 * 32 + wi] = __floats2half2_rn(c2[nt][0], c2[nt][1]);
            d_eprh[(size_t)e1 * 32 + wi] = __floats2half2_rn(c2[nt][2], c2[nt][3]);
            int col = nt * 8 + 2 * tig;
            float s0 = c2[nt][0] + c2[nt][2];
            float s1 = c2[nt][1] + c2[nt][3];
            float q0 = c2[nt][0] * c2[nt][0] + c2[nt][2] * c2[nt][2];
            float q1 = c2[nt][1] * c2[nt][1] + c2[nt][3] * c2[nt][3];
#pragma unroll
            for (int off = 4; off < 32; off <<= 1) {
                s0 += __shfl_xor_sync(FULLM, s0, off);
                s1 += __shfl_xor_sync(FULLM, s1, off);
                q0 += __shfl_xor_sync(FULLM, q0, off);
                q1 += __shfl_xor_sync(FULLM, q1, off);
            }
            if (l < 4) {
                atomicAdd(&sStats[col], s0);
                atomicAdd(&sStats[col + 1], s1);
                atomicAdd(&sStats[64 + col], q0);
                atomicAdd(&sStats[64 + col + 1], q1);
            }
        }

        // ---- cooperative permuted writes of s (bf16) and scores ----
        __syncthreads();
        {
            int r = tid >> 1, half = tid & 1;
            int p = sPermI[r];
            const float* rowp = sA + r * 68 + half * 32;
            unsigned wpk[16];
#pragma unroll
            for (int k = 0; k < 16; k++) {
                asm("cvt.rn.bf16x2.f32 %0, %1, %2;"
                    : "=r"(wpk[k]) : "f"(rowp[2 * k + 1]), "f"(rowp[2 * k]));
            }
            uint4* dst = (uint4*)(d_sbufp + (size_t)p * 32 + half * 16);
            dst[0] = make_uint4(wpk[0], wpk[1], wpk[2], wpk[3]);
            dst[1] = make_uint4(wpk[4], wpk[5], wpk[6], wpk[7]);
            dst[2] = make_uint4(wpk[8], wpk[9], wpk[10], wpk[11]);
            dst[3] = make_uint4(wpk[12], wpk[13], wpk[14], wpk[15]);
        }
        if (tid < 128) {
            int p = sPermI[tid];
            const float4* sp = (const float4*)(sScore + tid * 8);
            float4* dp = (float4*)(d_scoreb + (size_t)p * 8);
            dp[0] = sp[0];
            dp[1] = sp[1];
        }
        cur ^= 1;
        __syncthreads();
    }

    __syncthreads();
    if (tid < 64) {
        atomicAdd(&d_stats[tid], sStats[tid]);
        atomicAdd(&d_stats[64 + tid], sStats[64 + tid]);
    }
}

// ---------------- fused node kernel: sequential CSR streams ----------------
__global__ void __launch_bounds__(256) k_node_h1(const float* __restrict__ VeRow,
                                                 const float* __restrict__ dcoef,
                                                 const float* __restrict__ x,
                                                 const float* __restrict__ WOh,
                                                 const float* __restrict__ bOh) {
    __shared__ float sW[4096];
    __shared__ float ssum[64], ssq[64];
    int tid = threadIdx.x;
    for (int i = tid; i < 4096; i += 256) sW[i] = WOh[i];
    if (tid < 64) { ssum[tid] = 0.f; ssq[tid] = 0.f; }
    __syncthreads();

    int l = tid & 31;
    int n = blockIdx.x * 8 + (tid >> 5);
    if (n < NN) {
        int start = d_rowoff[n], end = d_rowoff[n + 1];
        int h0 = l >> 3;
        int wsel = l >> 1;
        float accV0 = 0.f, accV1 = 0.f, accR0 = 0.f, accR1 = 0.f, den0 = 0.f, den1 = 0.f;
        for (int j = start; j < end; j += 32) {
            int m = end - j; if (m > 32) m = 32;
            int s_l = (l < m) ? __ldg(&d_srcp[j + l]) : 0;
#pragma unroll 2
            for (int t = 0; t < m; t++) {
                int src = __shfl_sync(FULLM, s_l, t);
                size_t jj = (size_t)(j + t);
                float ex0 = __expf(__ldg(&d_scoreb[jj * 8 + h0]));
                float ex1 = __expf(__ldg(&d_scoreb[jj * 8 + h0 + 4]));
                den0 += ex0; den1 += ex1;
                accV0 += __ldg(&d_V[(size_t)src * 64 + l]) * ex0;
                accV1 += __ldg(&d_V[(size_t)src * 64 + 32 + l]) * ex1;
                unsigned wlo = __ldg(&d_sbufp[jj * 32 + wsel]);
                unsigned whi = __ldg(&d_sbufp[jj * 32 + 16 + wsel]);
                float sb0 = __uint_as_float((l & 1) ? (wlo & 0xffff0000u) : (wlo << 16));
                float sb1 = __uint_as_float((l & 1) ? (whi & 0xffff0000u) : (whi << 16));
                accR0 += sb0 * ex0;
                accR1 += sb1 * ex1;
            }
        }
        float inv0 = 1.f / (den0 + 1e-16f), inv1 = 1.f / (den1 + 1e-16f);
        float rv0 = accR0 * inv0, rv1 = accR1 * inv1;
        float out0 = accV0 * inv0, out1 = accV1 * inv1;

        int gbase = l & 24;
#pragma unroll
        for (int k = 0; k < 8; k++) {
            float r0 = __shfl_sync(FULLM, rv0, gbase + k);
            float r1 = __shfl_sync(FULLM, rv1, gbase + k);
            out0 += r0 * VeRow[k * 64 + l];
            out1 += r1 * VeRow[k * 64 + l + 32];
        }
        float deg = (float)(end - start);
        float ld = logf(deg + 1.f);
        out0 *= (dcoef[l * 2] + ld * dcoef[l * 2 + 1]);
        out1 *= (dcoef[(l + 32) * 2] + ld * dcoef[(l + 32) * 2 + 1]);

        float a0 = bOh[l] + x[n * 64 + l];
        float a1 = bOh[l + 32] + x[n * 64 + 32 + l];
#pragma unroll
        for (int d = 0; d < 32; d++) {
            float v = __shfl_sync(FULLM, out0, d);
            a0 += v * sW[d * 64 + l];
            a1 += v * sW[d * 64 + 32 + l];
        }
#pragma unroll
        for (int d = 0; d < 32; d++) {
            float v = __shfl_sync(FULLM, out1, d);
            a0 += v * sW[(d + 32) * 64 + l];
            a1 += v * sW[(d + 32) * 64 + 32 + l];
        }
        d_t1[n * 64 + l] = a0;
        d_t1[n * 64 + 32 + l] = a1;
        atomicAdd(&ssum[l], a0);
        atomicAdd(&ssq[l], a0 * a0);
        atomicAdd(&ssum[l + 32], a1);
        atomicAdd(&ssq[l + 32], a1 * a1);
    }
    __syncthreads();
    if (tid < 64) {
        atomicAdd(&d_stats[128 + tid], ssum[tid]);
        atomicAdd(&d_stats[192 + tid], ssq[tid]);
    }
}

// ---------------- fused MLP ----------------
__global__ void __launch_bounds__(256) k_mlp(const float* __restrict__ g1h,
                                             const float* __restrict__ be1h,
                                             const float* __restrict__ W1,
                                             const float* __restrict__ b1v,
                                             const float* __restrict__ W2,
                                             const float* __restrict__ b2v) {
    __shared__ float sW1[8192];
    __shared__ float sW2[8192];
    __shared__ float ssum[64], ssq[64];
    int tid = threadIdx.x;
    for (int i = tid; i < 8192; i += 256) { sW1[i] = W1[i]; sW2[i] = W2[i]; }
    if (tid < 64) { ssum[tid] = 0.f; ssq[tid] = 0.f; }
    __syncthreads();

    int l = tid & 31, w = tid >> 5;
    float mu0 = d_stats[128 + l] / NN;
    float mu1 = d_stats[160 + l] / NN;
    float var0 = d_stats[192 + l] / NN - mu0 * mu0;
    float var1 = d_stats[224 + l] / NN - mu1 * mu1;
    float sc0 = g1h[l] * rsqrtf(var0 + 1e-5f);
    float sc1 = g1h[l + 32] * rsqrtf(var1 + 1e-5f);
    float sh0 = be1h[l] - mu0 * sc0;
    float sh1 = be1h[l + 32] - mu1 * sc1;
    float bb0 = b1v[l], bb1 = b1v[l + 32], bb2 = b1v[l + 64], bb3 = b1v[l + 96];
    float b20 = b2v[l], b21 = b2v[l + 32];

    float lsum0 = 0.f, lsum1 = 0.f, lsq0 = 0.f, lsq1 = 0.f;
    int nbase = (blockIdx.x * 8 + w) * 4;
    for (int r = 0; r < 4; r++) {
        int n = nbase + r;
        if (n >= NN) break;
        float h10 = d_t1[n * 64 + l] * sc0 + sh0;
        float h11 = d_t1[n * 64 + 32 + l] * sc1 + sh1;
        float a0 = bb0, a1 = bb1, a2 = bb2, a3 = bb3;
#pragma unroll
        for (int d = 0; d < 32; d++) {
            float v = __shfl_sync(FULLM, h10, d);
            a0 += v * sW1[d * 128 + l];
            a1 += v * sW1[d * 128 + l + 32];
            a2 += v * sW1[d * 128 + l + 64];
            a3 += v * sW1[d * 128 + l + 96];
        }
#pragma unroll
        for (int d = 0; d < 32; d++) {
            float v = __shfl_sync(FULLM, h11, d);
            a0 += v * sW1[(d + 32) * 128 + l];
            a1 += v * sW1[(d + 32) * 128 + l + 32];
            a2 += v * sW1[(d + 32) * 128 + l + 64];
            a3 += v * sW1[(d + 32) * 128 + l + 96];
        }
        float m0 = fmaxf(a0, 0.f), m1 = fmaxf(a1, 0.f);
        float m2 = fmaxf(a2, 0.f), m3 = fmaxf(a3, 0.f);
        float f0 = b20, f1 = b21;
#pragma unroll
        for (int mm = 0; mm < 32; mm++) {
            float v = __shfl_sync(FULLM, m0, mm);
            f0 += v * sW2[mm * 64 + l];
            f1 += v * sW2[mm * 64 + 32 + l];
        }
#pragma unroll
        for (int mm = 0; mm < 32; mm++) {
            float v = __shfl_sync(FULLM, m1, mm);
            f0 += v * sW2[(mm + 32) * 64 + l];
            f1 += v * sW2[(mm + 32) * 64 + 32 + l];
        }
#pragma unroll
        for (int mm = 0; mm < 32; mm++) {
            float v = __shfl_sync(FULLM, m2, mm);
            f0 += v * sW2[(mm + 64) * 64 + l];
            f1 += v * sW2[(mm + 64) * 64 + 32 + l];
        }
#pragma unroll
        for (int mm = 0; mm < 32; mm++) {
            float v = __shfl_sync(FULLM, m3, mm);
            f0 += v * sW2[(mm + 96) * 64 + l];
            f1 += v * sW2[(mm + 96) * 64 + 32 + l];
        }
        float t0 = h10 + f0;
        float t1v = h11 + f1;
        d_t2[n * 64 + l] = t0;
        d_t2[n * 64 + 32 + l] = t1v;
        lsum0 += t0; lsum1 += t1v; lsq0 += t0 * t0; lsq1 += t1v * t1v;
    }
    atomicAdd(&ssum[l], lsum0);
    atomicAdd(&ssq[l], lsq0);
    atomicAdd(&ssum[l + 32], lsum1);
    atomicAdd(&ssq[l + 32], lsq1);
    __syncthreads();
    if (tid < 64) {
        atomicAdd(&d_stats[256 + tid], ssum[tid]);
        atomicAdd(&d_stats[320 + tid], ssq[tid]);
    }
}

// ---------------- final h output ----------------
__global__ void k_hout(const float* __restrict__ g2h,
                       const float* __restrict__ b2h, float* __restrict__ out) {
    int idx0 = blockIdx.x * blockDim.x + threadIdx.x;
    int stride = gridDim.x * blockDim.x;
    int col = idx0 & 63;
    float mu = d_stats[256 + col] / NN;
    float var = d_stats[320 + col] / NN - mu * mu;
    float sc = g2h[col] * rsqrtf(var + 1e-5f);
    float sh = b2h[col] - mu * sc;
    for (int i = idx0; i < NN * 64; i += stride) out[i] = d_t2[i] * sc + sh;
}

// ---------------- final e output (from fp16 epre) ----------------
__global__ void k_eout(const float* __restrict__ g1e,
                       const float* __restrict__ b1e, float* __restrict__ out) {
    int idx0 = blockIdx.x * blockDim.x + threadIdx.x;
    int stride = gridDim.x * blockDim.x;   // multiple of 32
    int cp = idx0 & 31;
    int c0 = 2 * cp, c1 = 2 * cp + 1;
    float mu0 = d_stats[c0] / NE, var0 = d_stats[64 + c0] / NE - mu0 * mu0;
    float mu1 = d_stats[c1] / NE, var1 = d_stats[64 + c1] / NE - mu1 * mu1;
    float sc0 = g1e[c0] * rsqrtf(var0 + 1e-5f);
    float sc1 = g1e[c1] * rsqrtf(var1 + 1e-5f);
    float sh0 = b1e[c0] - mu0 * sc0;
    float sh1 = b1e[c1] - mu1 * sc1;
    const int total = NE * 32;
    for (int i = idx0; i < total; i += stride) {
        float2 v = __half22float2(d_eprh[i]);
        *(float2*)(out + (size_t)i * 2) = make_float2(v.x * sc0 + sh0, v.y * sc1 + sh1);
    }
}

// ---------------- launch ----------------
extern "C" void kernel_launch(void* const* d_in, const int* in_sizes, int n_in,
                              void* d_out, int out_size) {
    const float* x     = (const float*)d_in[0];
    const float* ea    = (const float*)d_in[1];
    const int*   eidx  = (const int*)d_in[2];
    const float* Wq    = (const float*)d_in[3];
    const float* bq    = (const float*)d_in[4];
    const float* Wk    = (const float*)d_in[5];
    const float* We    = (const float*)d_in[6];
    const float* be    = (const float*)d_in[7];
    const float* Wv    = (const float*)d_in[8];
    const float* Aw    = (const float*)d_in[9];
    const float* VeRow = (const float*)d_in[10];
    const float* dcoef = (const float*)d_in[11];
    const float* WOh   = (const float*)d_in[12];
    const float* bOh   = (const float*)d_in[13];
    const float* WOe   = (const float*)d_in[14];
    const float* bOe   = (const float*)d_in[15];
    const float* g1h   = (const float*)d_in[16];
    const float* b1h   = (const float*)d_in[17];
    const float* g1e   = (const float*)d_in[18];
    const float* b1e   = (const float*)d_in[19];
    const float* W1    = (const float*)d_in[20];
    const float* b1v   = (const float*)d_in[21];
    const float* W2    = (const float*)d_in[22];
    const float* b2v   = (const float*)d_in[23];
    const float* g2h   = (const float*)d_in[24];
    const float* b2h   = (const float*)d_in[25];
    float* out = (float*)d_out;

    const int edge_smem = 31744 * 4;  // 126,976 B
    cudaFuncSetAttribute(k_edge_mma, cudaFuncAttributeMaxDynamicSharedMemorySize, edge_smem);

    k_zero<<<196, 256>>>();
    k_count<<<3125, 256>>>(eidx);
    k_scan<<<1, 1024>>>();
    k_fill<<<3125, 256>>>(eidx);
    k_qkv<<<1563, 256>>>(x, Wq, bq, Wk, Wv);
    k_edge_mma<<<148, 256, edge_smem>>>(ea, eidx, We, be, Aw, WOe, bOe);
    k_node_h1<<<6250, 256>>>(VeRow, dcoef, x, WOh, bOh);
    k_mlp<<<1563, 256>>>(g1h, b1h, W1, b1v, W2, b2v);
    k_hout<<<512, 256>>>(g2h, b2h, out);
    k_eout<<<4096, 256>>>(g1e, b1e, out + (size_t)NN * 64);
}